// round 4
// baseline (speedup 1.0000x reference)
#include <cuda_runtime.h>
#include <cuda_bf16.h>
#include <cstdint>

#define N_NODES_MAX 100000
#define DSIGMA_DT (-0.0001f)
#define PHI_THRESH 0.3f
#define EPS 1e-8f

// Scratch: packed {pos.x, pos.y, pos.z, T} per node, and {num.xyz, cnt} accumulator.
__device__ float4 g_packed[N_NODES_MAX];
__device__ float4 g_acc[N_NODES_MAX];
__device__ int g_idx_is64;

// One kernel: zero accumulators, pack pos+T into float4, detect index dtype.
__global__ void prep_kernel(const float* __restrict__ x,
                            const float* __restrict__ pos,
                            const unsigned int* __restrict__ ei_words,
                            int n_nodes) {
    int i = blockIdx.x * blockDim.x + threadIdx.x;
    if (i < n_nodes) {
        // Independent loads -> issued concurrently (MLP 4).
        float p0 = pos[i * 3 + 0];
        float p1 = pos[i * 3 + 1];
        float p2 = pos[i * 3 + 2];
        float t  = __ldg(&x[i * 9 + 3]);
        g_acc[i] = make_float4(0.f, 0.f, 0.f, 0.f);
        g_packed[i] = make_float4(p0, p1, p2, t);
    }
    if (blockIdx.x == 0 && threadIdx.x == 0) {
        // int64 little-endian with values < 2^31 => odd 32-bit words all zero.
        unsigned int acc = 0;
        #pragma unroll
        for (int k = 0; k < 64; k++) {
            acc |= ei_words[2 * k + 1];
        }
        g_idx_is64 = (acc == 0) ? 1 : 0;
    }
}

__device__ __forceinline__ void edge_body(int src, int dst) {
    float4 a = __ldg(&g_packed[src]);
    float4 b = __ldg(&g_packed[dst]);

    float dT = a.w - b.w;
    float px = a.x - b.x;
    float py = a.y - b.y;
    float pz = a.z - b.z;

    float dist2 = px * px + py * py + pz * pz + EPS;
    float w = dT / dist2;

    float4* addr = &g_acc[dst];
    asm volatile("red.global.add.v4.f32 [%0], {%1, %2, %3, %4};"
                 :: "l"(addr), "f"(w * px), "f"(w * py), "f"(w * pz), "f"(1.0f)
                 : "memory");
}

// 2 edges per thread: vectorized index loads (evict-first), batched gathers.
__global__ __launch_bounds__(256) void edge_scatter_kernel(
        const void* __restrict__ edge_index, int n_edges) {
    int base = (blockIdx.x * blockDim.x + threadIdx.x) * 2;
    if (base >= n_edges) return;

    int s0, d0, s1, d1;
    bool two = (base + 1 < n_edges);

    if (g_idx_is64) {
        const long long* ei = (const long long*)edge_index;
        if (two) {
            longlong2 sv = __ldcs((const longlong2*)&ei[base]);
            longlong2 dv = __ldcs((const longlong2*)&ei[n_edges + base]);
            s0 = (int)sv.x; s1 = (int)sv.y;
            d0 = (int)dv.x; d1 = (int)dv.y;
        } else {
            s0 = (int)__ldcs(&ei[base]);
            d0 = (int)__ldcs(&ei[n_edges + base]);
            s1 = s0; d1 = d0;
        }
    } else {
        const int* ei = (const int*)edge_index;
        if (two) {
            int2 sv = __ldcs((const int2*)&ei[base]);
            int2 dv = __ldcs((const int2*)&ei[n_edges + base]);
            s0 = sv.x; s1 = sv.y;
            d0 = dv.x; d1 = dv.y;
        } else {
            s0 = __ldcs(&ei[base]);
            d0 = __ldcs(&ei[n_edges + base]);
            s1 = s0; d1 = d0;
        }
    }

    // All 4 gathers issued back-to-back (independent) before compute.
    float4 a0 = __ldg(&g_packed[s0]);
    float4 b0 = __ldg(&g_packed[d0]);
    float4 a1 = __ldg(&g_packed[s1]);
    float4 b1 = __ldg(&g_packed[d1]);

    {
        float dT = a0.w - b0.w;
        float px = a0.x - b0.x, py = a0.y - b0.y, pz = a0.z - b0.z;
        float w = dT / (px * px + py * py + pz * pz + EPS);
        float4* addr = &g_acc[d0];
        asm volatile("red.global.add.v4.f32 [%0], {%1, %2, %3, %4};"
                     :: "l"(addr), "f"(w * px), "f"(w * py), "f"(w * pz), "f"(1.0f)
                     : "memory");
    }
    if (two) {
        float dT = a1.w - b1.w;
        float px = a1.x - b1.x, py = a1.y - b1.y, pz = a1.z - b1.z;
        float w = dT / (px * px + py * py + pz * pz + EPS);
        float4* addr = &g_acc[d1];
        asm volatile("red.global.add.v4.f32 [%0], {%1, %2, %3, %4};"
                     :: "l"(addr), "f"(w * px), "f"(w * py), "f"(w * pz), "f"(1.0f)
                     : "memory");
    }
}

__global__ void finalize_kernel(const float* __restrict__ x,
                                float* __restrict__ out,
                                int n_nodes) {
    int i = blockIdx.x * blockDim.x + threadIdx.x;
    if (i >= n_nodes) return;

    float4 a = g_acc[i];
    float phi = __ldg(&x[i * 9 + 8]);

    float cnt = fmaxf(a.w, 1.0f);
    float inv = 1.0f / cnt;
    float mask = (fabsf(phi) < PHI_THRESH) ? 1.0f : 0.0f;
    float s = DSIGMA_DT * inv * mask;

    out[i * 3 + 0] = s * a.x;
    out[i * 3 + 1] = s * a.y;
    out[i * 3 + 2] = s * a.z;
}

extern "C" void kernel_launch(void* const* d_in, const int* in_sizes, int n_in,
                              void* d_out, int out_size) {
    const float* x = (const float*)d_in[0];    // [N, 9]
    const float* pos = (const float*)d_in[1];  // [N, 3]
    const void* edge_index = d_in[2];          // [2, E] int32 or int64

    int n_nodes = in_sizes[1] / 3;
    int n_edges = in_sizes[2] / 2;

    float* out = (float*)d_out;

    const int TPB = 256;
    prep_kernel<<<(n_nodes + TPB - 1) / TPB, TPB>>>(
        x, pos, (const unsigned int*)edge_index, n_nodes);
    int edge_threads = (n_edges + 1) / 2;
    edge_scatter_kernel<<<(edge_threads + TPB - 1) / TPB, TPB>>>(edge_index, n_edges);
    finalize_kernel<<<(n_nodes + TPB - 1) / TPB, TPB>>>(x, out, n_nodes);
}